// round 4
// baseline (speedup 1.0000x reference)
#include <cuda_runtime.h>
#include <cuda_bf16.h>
#include <stdint.h>

// GCN 2-layer, CSR-gather formulation (no feature atomics):
//   g    = (x @ W) * dinv[row]           (dinv = rsqrt(indeg+1))
//   y[d] = dinv[d] * (g[d] + sum_{e:dst=d} g[src_e]) + b

#define NMAX 100097
#define EMAX 3200064
#define F_IN 128
#define H1 32
#define H2 16

__device__ float g_dinv[NMAX];
__device__ float g_g1[NMAX * H1];
__device__ float g_g2[NMAX * H2];
__device__ int   g_rowptr[NMAX + 1];
__device__ int   g_pos[NMAX];
__device__ int   g_colidx[EMAX];

// ------------------------------------------------------------- CSR build ----
__global__ void k_zero(int n) {
    int i = blockIdx.x * blockDim.x + threadIdx.x;
    if (i < n) g_pos[i] = 0;
}

__global__ void k_hist(const int* __restrict__ dst, int E) {
    int e = blockIdx.x * blockDim.x + threadIdx.x;
    if (e < E) atomicAdd(&g_pos[dst[e]], 1);  // no-return -> RED
}

// Single-block exclusive scan over counts. Also produces dinv and primes pos
// with the row start offsets for the fill pass.
__global__ void __launch_bounds__(1024) k_scan(int n, int E) {
    __shared__ int ssum[1024];
    int tid = threadIdx.x;
    int per = (n + 1023) >> 10;
    int s = tid * per, e = min(s + per, n);

    int sum = 0;
    for (int i = s; i < e; i++) sum += g_pos[i];
    ssum[tid] = sum;
    __syncthreads();
    for (int off = 1; off < 1024; off <<= 1) {   // inclusive Hillis-Steele
        int v = (tid >= off) ? ssum[tid - off] : 0;
        __syncthreads();
        ssum[tid] += v;
        __syncthreads();
    }
    int run = (tid > 0) ? ssum[tid - 1] : 0;

    for (int i = s; i < e; i++) {
        int c = g_pos[i];
        g_rowptr[i] = run;
        g_pos[i]    = run;
        g_dinv[i]   = rsqrtf((float)c + 1.0f);
        run += c;
    }
    if (tid == 0) g_rowptr[n] = E;
}

__global__ void k_fill(const int* __restrict__ src, const int* __restrict__ dst, int E) {
    int e = blockIdx.x * blockDim.x + threadIdx.x;
    if (e < E) {
        int p = atomicAdd(&g_pos[dst[e]], 1);
        g_colidx[p] = src[e];
    }
}

// ------------------------------------------------------------- layer 1 ------
// Register-tiled GEMM: thread = 4 rows x 4 cols; warp = 4 rowgroups x 8
// colgroups -> 16 rows; block (8 warps) -> 128 rows. xv prefetched.
__global__ void __launch_bounds__(256) k_gemm1(const float* __restrict__ x,
                                               const float* __restrict__ W1, int n) {
    __shared__ float Ws[F_IN * H1];   // 16 KB
    int tid = threadIdx.x;
    for (int i = tid; i < F_IN * H1; i += 256) Ws[i] = W1[i];
    __syncthreads();

    int lane = tid & 31, warp = tid >> 5;
    int c0 = (lane & 7) * 4;
    int rg = lane >> 3;
    int rowbase = blockIdx.x * 128 + warp * 16 + rg * 4;

    const float* xp[4];
    int rows[4];
#pragma unroll
    for (int r = 0; r < 4; r++) {
        int row = rowbase + r;
        rows[r] = row;
        int rc = row < n ? row : n - 1;  // clamp (tail only)
        xp[r] = x + (size_t)rc * F_IN;
    }

    float acc[4][4] = {};
    float4 xv[4];
#pragma unroll
    for (int r = 0; r < 4; r++) xv[r] = __ldg((const float4*)xp[r]);

#pragma unroll
    for (int k4 = 0; k4 < F_IN; k4 += 4) {
        float4 cur[4];
#pragma unroll
        for (int r = 0; r < 4; r++) cur[r] = xv[r];
        if (k4 + 4 < F_IN) {
#pragma unroll
            for (int r = 0; r < 4; r++) xv[r] = __ldg((const float4*)(xp[r] + k4 + 4));
        }
        float4 w0 = *(const float4*)&Ws[(k4 + 0) * H1 + c0];
        float4 w1 = *(const float4*)&Ws[(k4 + 1) * H1 + c0];
        float4 w2 = *(const float4*)&Ws[(k4 + 2) * H1 + c0];
        float4 w3 = *(const float4*)&Ws[(k4 + 3) * H1 + c0];
#pragma unroll
        for (int r = 0; r < 4; r++) {
            acc[r][0] = fmaf(cur[r].x, w0.x, acc[r][0]);
            acc[r][1] = fmaf(cur[r].x, w0.y, acc[r][1]);
            acc[r][2] = fmaf(cur[r].x, w0.z, acc[r][2]);
            acc[r][3] = fmaf(cur[r].x, w0.w, acc[r][3]);
            acc[r][0] = fmaf(cur[r].y, w1.x, acc[r][0]);
            acc[r][1] = fmaf(cur[r].y, w1.y, acc[r][1]);
            acc[r][2] = fmaf(cur[r].y, w1.z, acc[r][2]);
            acc[r][3] = fmaf(cur[r].y, w1.w, acc[r][3]);
            acc[r][0] = fmaf(cur[r].z, w2.x, acc[r][0]);
            acc[r][1] = fmaf(cur[r].z, w2.y, acc[r][1]);
            acc[r][2] = fmaf(cur[r].z, w2.z, acc[r][2]);
            acc[r][3] = fmaf(cur[r].z, w2.w, acc[r][3]);
            acc[r][0] = fmaf(cur[r].w, w3.x, acc[r][0]);
            acc[r][1] = fmaf(cur[r].w, w3.y, acc[r][1]);
            acc[r][2] = fmaf(cur[r].w, w3.z, acc[r][2]);
            acc[r][3] = fmaf(cur[r].w, w3.w, acc[r][3]);
        }
    }

#pragma unroll
    for (int r = 0; r < 4; r++) {
        int row = rows[r];
        if (row < n) {
            float di = g_dinv[row];
            float4 v = make_float4(acc[r][0] * di, acc[r][1] * di,
                                   acc[r][2] * di, acc[r][3] * di);
            *(float4*)&g_g1[row * H1 + c0] = v;
        }
    }
}

// Gather layer 1 + relu + GEMM2 fused. Warp per dst node, lane = col.
__global__ void __launch_bounds__(256) k_gather1_gemm2(const float* __restrict__ W2,
                                                       const float* __restrict__ b1,
                                                       float* __restrict__ out, int n) {
    __shared__ float W2s[H1 * H2];
    __shared__ float b1s[H1];
    int tid = threadIdx.x;
    for (int i = tid; i < H1 * H2; i += 256) W2s[i] = W2[i];
    if (tid < H1) b1s[tid] = b1[tid];
    __syncthreads();

    int warp = tid >> 5, lane = tid & 31;
    int d = blockIdx.x * 8 + warp;
    if (d >= n) return;

    int start = g_rowptr[d], end = g_rowptr[d + 1];
    float a0 = g_g1[d * H1 + lane];  // self loop
    float a1 = 0.f, a2 = 0.f, a3 = 0.f;

    for (int base = start; base < end; base += 32) {
        int ii = base + lane;
        int idx = (ii < end) ? __ldg(&g_colidx[ii]) : 0;
        int cnt = min(32, end - base);
        int j = 0;
        for (; j + 4 <= cnt; j += 4) {
            int s0 = __shfl_sync(0xffffffffu, idx, j);
            int s1 = __shfl_sync(0xffffffffu, idx, j + 1);
            int s2 = __shfl_sync(0xffffffffu, idx, j + 2);
            int s3 = __shfl_sync(0xffffffffu, idx, j + 3);
            a0 += g_g1[s0 * H1 + lane];
            a1 += g_g1[s1 * H1 + lane];
            a2 += g_g1[s2 * H1 + lane];
            a3 += g_g1[s3 * H1 + lane];
        }
        for (; j < cnt; j++) {
            int s = __shfl_sync(0xffffffffu, idx, j);
            a0 += g_g1[s * H1 + lane];
        }
    }

    float di = g_dinv[d];
    float h = fmaxf(fmaf(di, (a0 + a1) + (a2 + a3), b1s[lane]), 0.0f);

    float acc = 0.0f;
    int j = lane & 15;
#pragma unroll
    for (int k = 0; k < H1; k++) {
        float v = __shfl_sync(0xffffffffu, h, k);
        acc = fmaf(v, W2s[k * H2 + j], acc);
    }
    if (lane < H2) {
        float g = acc * di;
        g_g2[d * H2 + lane] = g;
        out[d * H2 + lane]  = g;
    }
}

// Gather layer 2 + bias fused. Warp per dst node; lanes 0-15 hold cols, all
// 32 lanes cooperate on edge-index loads.
__global__ void __launch_bounds__(256) k_gather2(const float* __restrict__ b2,
                                                 float* __restrict__ out, int n) {
    int tid = threadIdx.x;
    int warp = tid >> 5, lane = tid & 31;
    int d = blockIdx.x * 8 + warp;
    if (d >= n) return;

    int start = g_rowptr[d], end = g_rowptr[d + 1];
    int l = lane & 15;
    float a0 = (lane < 16) ? g_g2[d * H2 + l] : 0.f;  // self loop
    float a1 = 0.f, a2 = 0.f, a3 = 0.f;

    for (int base = start; base < end; base += 32) {
        int ii = base + lane;
        int idx = (ii < end) ? __ldg(&g_colidx[ii]) : 0;
        int cnt = min(32, end - base);
        int j = 0;
        for (; j + 4 <= cnt; j += 4) {
            int s0 = __shfl_sync(0xffffffffu, idx, j);
            int s1 = __shfl_sync(0xffffffffu, idx, j + 1);
            int s2 = __shfl_sync(0xffffffffu, idx, j + 2);
            int s3 = __shfl_sync(0xffffffffu, idx, j + 3);
            if (lane < 16) {
                a0 += g_g2[s0 * H2 + l];
                a1 += g_g2[s1 * H2 + l];
                a2 += g_g2[s2 * H2 + l];
                a3 += g_g2[s3 * H2 + l];
            }
        }
        for (; j < cnt; j++) {
            int s = __shfl_sync(0xffffffffu, idx, j);
            if (lane < 16) a0 += g_g2[s * H2 + l];
        }
    }
    if (lane < 16) {
        out[d * H2 + l] = fmaf(g_dinv[d], (a0 + a1) + (a2 + a3), __ldg(&b2[l]));
    }
}

// ------------------------------------------------------------------ host ----
extern "C" void kernel_launch(void* const* d_in, const int* in_sizes, int n_in,
                              void* d_out, int out_size) {
    const float* x  = (const float*)d_in[0];
    const int*   ei = (const int*)d_in[1];
    const float* W1 = (const float*)d_in[2];
    const float* b1 = (const float*)d_in[3];
    const float* W2 = (const float*)d_in[4];
    const float* b2 = (const float*)d_in[5];
    float* out = (float*)d_out;

    int n = in_sizes[0] / F_IN;   // 100000
    int E = in_sizes[1] / 2;      // 3200000
    const int* src = ei;
    const int* dst = ei + E;

    k_zero<<<(n + 255) / 256, 256>>>(n);
    k_hist<<<(E + 255) / 256, 256>>>(dst, E);
    k_scan<<<1, 1024>>>(n, E);
    k_fill<<<(E + 255) / 256, 256>>>(src, dst, E);

    k_gemm1<<<(n + 127) / 128, 256>>>(x, W1, n);
    k_gather1_gemm2<<<(n + 7) / 8, 256>>>(W2, b1, out, n);
    k_gather2<<<(n + 7) / 8, 256>>>(b2, out, n);
}

// round 7
// speedup vs baseline: 1.7443x; 1.7443x over previous
#include <cuda_runtime.h>
#include <cuda_bf16.h>
#include <stdint.h>

// GCN 2-layer, atomic-scatter formulation:
//   g   = (x @ W) * dinv[row]           (dinv = rsqrt(indeg+1))
//   acc[d] = g[d] + sum_{e:dst=d} g[src_e]      (red.global.add.v4)
//   y   = dinv[d] * acc[d] + b

#define NMAX 100096
#define F_IN 128
#define H1 32
#define H2 16

__device__ float g_cnt[NMAX];         // degree+1 (float)
__device__ float g_dinv[NMAX];
__device__ float g_g1[NMAX * H1];
__device__ float g_acc1[NMAX * H1];
__device__ float g_g2[NMAX * H2];

// ---------------------------------------------------------------- degree ----
__global__ void k_init_deg(int n) {
    int i = blockIdx.x * blockDim.x + threadIdx.x;
    if (i < n) g_cnt[i] = 1.0f;  // self loop
}

__global__ void k_count_deg(const int* __restrict__ dst, int E) {
    int e = blockIdx.x * blockDim.x + threadIdx.x;
    if (e < E) atomicAdd(&g_cnt[dst[e]], 1.0f);  // no-return -> RED
}

// ------------------------------------------------------------- layer 1 ------
// Register-tiled GEMM: thread = 4 rows x 4 cols; warp = 4 rowgroups x 8
// colgroups -> 16 rows; block (8 warps) -> 128 rows. x prefetched one k4
// ahead. Also computes and stores dinv, and initializes acc1 = g1.
__global__ void __launch_bounds__(256) k_gemm1(const float* __restrict__ x,
                                               const float* __restrict__ W1, int n) {
    __shared__ float Ws[F_IN * H1];   // 16 KB
    int tid = threadIdx.x;
    for (int i = tid; i < F_IN * H1; i += 256) Ws[i] = W1[i];
    __syncthreads();

    int lane = tid & 31, warp = tid >> 5;
    int c0 = (lane & 7) * 4;
    int rg = lane >> 3;
    int rowbase = blockIdx.x * 128 + warp * 16 + rg * 4;

    const float* xp[4];
#pragma unroll
    for (int r = 0; r < 4; r++) {
        int rc = rowbase + r;
        rc = rc < n ? rc : n - 1;  // clamp (tail only)
        xp[r] = x + (size_t)rc * F_IN;
    }

    float acc[4][4] = {};
    float4 xv[4];
#pragma unroll
    for (int r = 0; r < 4; r++) xv[r] = __ldg((const float4*)xp[r]);

#pragma unroll
    for (int k4 = 0; k4 < F_IN; k4 += 4) {
        float4 cur[4];
#pragma unroll
        for (int r = 0; r < 4; r++) cur[r] = xv[r];
        if (k4 + 4 < F_IN) {
#pragma unroll
            for (int r = 0; r < 4; r++) xv[r] = __ldg((const float4*)(xp[r] + k4 + 4));
        }
        float4 w0 = *(const float4*)&Ws[(k4 + 0) * H1 + c0];
        float4 w1 = *(const float4*)&Ws[(k4 + 1) * H1 + c0];
        float4 w2 = *(const float4*)&Ws[(k4 + 2) * H1 + c0];
        float4 w3 = *(const float4*)&Ws[(k4 + 3) * H1 + c0];
#pragma unroll
        for (int r = 0; r < 4; r++) {
            acc[r][0] = fmaf(cur[r].x, w0.x, acc[r][0]);
            acc[r][1] = fmaf(cur[r].x, w0.y, acc[r][1]);
            acc[r][2] = fmaf(cur[r].x, w0.z, acc[r][2]);
            acc[r][3] = fmaf(cur[r].x, w0.w, acc[r][3]);
            acc[r][0] = fmaf(cur[r].y, w1.x, acc[r][0]);
            acc[r][1] = fmaf(cur[r].y, w1.y, acc[r][1]);
            acc[r][2] = fmaf(cur[r].y, w1.z, acc[r][2]);
            acc[r][3] = fmaf(cur[r].y, w1.w, acc[r][3]);
            acc[r][0] = fmaf(cur[r].z, w2.x, acc[r][0]);
            acc[r][1] = fmaf(cur[r].z, w2.y, acc[r][1]);
            acc[r][2] = fmaf(cur[r].z, w2.z, acc[r][2]);
            acc[r][3] = fmaf(cur[r].z, w2.w, acc[r][3]);
            acc[r][0] = fmaf(cur[r].w, w3.x, acc[r][0]);
            acc[r][1] = fmaf(cur[r].w, w3.y, acc[r][1]);
            acc[r][2] = fmaf(cur[r].w, w3.z, acc[r][2]);
            acc[r][3] = fmaf(cur[r].w, w3.w, acc[r][3]);
        }
    }

#pragma unroll
    for (int r = 0; r < 4; r++) {
        int row = rowbase + r;
        if (row < n) {
            float di = rsqrtf(g_cnt[row]);
            if (c0 == 0) g_dinv[row] = di;  // one writer per row (colgroup 0)
            float4 v = make_float4(acc[r][0] * di, acc[r][1] * di,
                                   acc[r][2] * di, acc[r][3] * di);
            *(float4*)&g_g1[row * H1 + c0]   = v;
            *(float4*)&g_acc1[row * H1 + c0] = v;
        }
    }
}

// per-edge scatter: acc1[dst] += g1[src]  (32 floats = 8 x red.v4)
__global__ void k_scatter1(const int* __restrict__ src, const int* __restrict__ dst, int E) {
    long long tid = (long long)blockIdx.x * blockDim.x + threadIdx.x;
    if (tid >= (long long)E * 8) return;
    int e = (int)(tid >> 3), c = (int)(tid & 7);
    int s = __ldg(&src[e]);
    int d = __ldg(&dst[e]);
    float4 v = ((const float4*)(g_g1 + s * H1))[c];
    float* p = g_acc1 + d * H1 + c * 4;
    asm volatile("red.global.add.v4.f32 [%0], {%1,%2,%3,%4};"
                 :: "l"(p), "f"(v.x), "f"(v.y), "f"(v.z), "f"(v.w) : "memory");
}

// epilogue layer1 + GEMM2 fused (warp shuffles), writes g2 and out self-loop.
__global__ void k_finish1_gemm2(const float* __restrict__ W2, const float* __restrict__ b1,
                                float* __restrict__ out, int n) {
    __shared__ float W2s[H1 * H2];  // 2 KB
    __shared__ float b1s[H1];
    int tid = threadIdx.x;  // 256
    for (int i = tid; i < H1 * H2; i += 256) W2s[i] = W2[i];
    if (tid < H1) b1s[tid] = b1[tid];
    __syncthreads();

    int warp = tid >> 5, lane = tid & 31;
    int row = blockIdx.x * 8 + warp;
    if (row >= n) return;

    float di = g_dinv[row];
    float h = fmaxf(fmaf(di, g_acc1[row * H1 + lane], b1s[lane]), 0.0f);

    float acc = 0.0f;
    int j = lane & 15;
#pragma unroll
    for (int k = 0; k < H1; k++) {
        float v = __shfl_sync(0xffffffffu, h, k);
        acc = fmaf(v, W2s[k * H2 + j], acc);
    }
    if (lane < H2) {
        float g = acc * di;
        g_g2[row * H2 + lane] = g;
        out[row * H2 + lane]  = g;
    }
}

// per-edge scatter layer 2: out[dst] += g2[src]  (16 floats = 4 x red.v4)
__global__ void k_scatter2(const int* __restrict__ src, const int* __restrict__ dst,
                           float* __restrict__ out, int E) {
    long long tid = (long long)blockIdx.x * blockDim.x + threadIdx.x;
    if (tid >= (long long)E * 4) return;
    int e = (int)(tid >> 2), c = (int)(tid & 3);
    int s = __ldg(&src[e]);
    int d = __ldg(&dst[e]);
    float4 v = ((const float4*)(g_g2 + s * H2))[c];
    float* p = out + d * H2 + c * 4;
    asm volatile("red.global.add.v4.f32 [%0], {%1,%2,%3,%4};"
                 :: "l"(p), "f"(v.x), "f"(v.y), "f"(v.z), "f"(v.w) : "memory");
}

__global__ void k_finish2(float* __restrict__ out, const float* __restrict__ b2, int total) {
    int i = blockIdx.x * blockDim.x + threadIdx.x;
    if (i < total) {
        out[i] = fmaf(g_dinv[i >> 4], out[i], __ldg(&b2[i & 15]));
    }
}

// ------------------------------------------------------------------ host ----
extern "C" void kernel_launch(void* const* d_in, const int* in_sizes, int n_in,
                              void* d_out, int out_size) {
    const float* x  = (const float*)d_in[0];
    const int*   ei = (const int*)d_in[1];
    const float* W1 = (const float*)d_in[2];
    const float* b1 = (const float*)d_in[3];
    const float* W2 = (const float*)d_in[4];
    const float* b2 = (const float*)d_in[5];
    float* out = (float*)d_out;

    int n = in_sizes[0] / F_IN;   // 100000
    int E = in_sizes[1] / 2;      // 3200000
    const int* src = ei;
    const int* dst = ei + E;

    k_init_deg<<<(n + 255) / 256, 256>>>(n);
    k_count_deg<<<(E + 255) / 256, 256>>>(dst, E);

    k_gemm1<<<(n + 127) / 128, 256>>>(x, W1, n);
    k_scatter1<<<(int)(((long long)E * 8 + 255) / 256), 256>>>(src, dst, E);
    k_finish1_gemm2<<<(n + 7) / 8, 256>>>(W2, b1, out, n);
    k_scatter2<<<(int)(((long long)E * 4 + 255) / 256), 256>>>(src, dst, out, E);
    k_finish2<<<(n * H2 + 255) / 256, 256>>>(out, b2, n * H2);
}